// round 12
// baseline (speedup 1.0000x reference)
#include <cuda_runtime.h>
#include <cuda_fp16.h>
#include <stdint.h>
#include <math.h>

#define BB 64
#define LL 196
#define DD 2048
#define II 512
#define MM (BB * LL)   // 12544

typedef __half f16;

// ---------------- device scratch (allocation-free) ----------------
__device__ f16 g_fv_h[(size_t)MM * DD];
__device__ f16 g_fvs_h[(size_t)MM * II];
__device__ f16 g_WfT_h[(size_t)II * DD];   // [I, D] K-major
__device__ f16 g_WaT_h[(size_t)DD * II];   // [D, I] K-major
__device__ float g_hs[BB * II];
__device__ float g_sum[BB * DD];           // softmax denominators (memset each run)

// ---------------- helpers ----------------
__device__ __forceinline__ uint32_t smem_u32(const void* p) {
    uint32_t a;
    asm("{ .reg .u64 t; cvta.to.shared.u64 t, %1; cvt.u32.u64 %0, t; }"
        : "=r"(a) : "l"(p));
    return a;
}
__device__ __forceinline__ void cp_async16(uint32_t s, const void* g) {
    asm volatile("cp.async.cg.shared.global [%0], [%1], 16;" :: "r"(s), "l"(g));
}
__device__ __forceinline__ void cp_commit() {
    asm volatile("cp.async.commit_group;" ::: "memory");
}
__device__ __forceinline__ void cp_wait1() {
    asm volatile("cp.async.wait_group 1;" ::: "memory");
}
__device__ __forceinline__ void cp_wait0() {
    asm volatile("cp.async.wait_group 0;" ::: "memory");
}
__device__ __forceinline__ void ldsm4(uint32_t& r0, uint32_t& r1, uint32_t& r2,
                                      uint32_t& r3, uint32_t addr) {
    asm volatile("ldmatrix.sync.aligned.m8n8.x4.shared.b16 {%0,%1,%2,%3}, [%4];"
                 : "=r"(r0), "=r"(r1), "=r"(r2), "=r"(r3) : "r"(addr));
}
__device__ __forceinline__ void mma16816(float* c, const uint32_t* a,
                                         const uint32_t* b) {
    asm volatile(
        "mma.sync.aligned.m16n8k16.row.col.f32.f16.f16.f32 "
        "{%0,%1,%2,%3}, {%4,%5,%6,%7}, {%8,%9}, {%0,%1,%2,%3};"
        : "+f"(c[0]), "+f"(c[1]), "+f"(c[2]), "+f"(c[3])
        : "r"(a[0]), "r"(a[1]), "r"(a[2]), "r"(a[3]), "r"(b[0]), "r"(b[1]));
}

// ---------------- fused prep kernel ----------------
// blocks [0,1024): transpose Wf [2048,512] -> WfT [512,2048]
// blocks [1024,2048): transpose Wa [512,2048] -> WaT [2048,512]
// blocks [2048,2176): hs = hidden @ Wh + bh
// blocks [2176,...): fv -> fp16
__device__ __forceinline__ void transpose_body(const float* __restrict__ in,
                                               f16* __restrict__ oh,
                                               int K, int N, int bx, int by,
                                               int tid, float (*t)[33]) {
    int n0 = bx * 32, k0 = by * 32;
    int tx = tid & 31, ty = tid >> 5;   // (32, 8)
#pragma unroll
    for (int i = 0; i < 32; i += 8)
        t[ty + i][tx] = in[(size_t)(k0 + ty + i) * N + n0 + tx];
    __syncthreads();
#pragma unroll
    for (int i = 0; i < 32; i += 8)
        oh[(size_t)(n0 + ty + i) * K + k0 + tx] = __float2half_rn(t[tx][ty + i]);
}

__global__ __launch_bounds__(256)
void prep_kernel(const float* __restrict__ fv, const float* __restrict__ hidden,
                 const float* __restrict__ Wh, const float* __restrict__ bh,
                 const float* __restrict__ Wf, const float* __restrict__ Wa) {
    __shared__ float t[32][33];
    int blk = blockIdx.x, tid = threadIdx.x;
    if (blk < 1024) {
        transpose_body(Wf, g_WfT_h, DD, II, blk & 15, blk >> 4, tid, t);
    } else if (blk < 2048) {
        int bb = blk - 1024;
        transpose_body(Wa, g_WaT_h, II, DD, bb & 63, bb >> 6, tid, t);
    } else if (blk < 2176) {
        int idx = (blk - 2048) * 256 + tid;   // 0..BB*II
        int b = idx >> 9, i = idx & 511;
        const float* h = hidden + b * II;
        float acc = bh[i];
#pragma unroll 4
        for (int j = 0; j < II; ++j)
            acc = fmaf(h[j], Wh[j * II + i], acc);
        g_hs[idx] = acc;
    } else {
        size_t i = (size_t)(blk - 2176) * 256 + tid;   // over MM*DD/4
        float4 v = ((const float4*)fv)[i];
        ((__half2*)g_fv_h)[2 * i]     = __floats2half2_rn(v.x, v.y);
        ((__half2*)g_fv_h)[2 * i + 1] = __floats2half2_rn(v.z, v.w);
    }
}
#define PREP_BLOCKS (2176 + (MM * DD / 4) / 256)

// ---------------- tensor-core (mma.sync) GEMM ----------------
// C = A@B^T; A [M,K0] fp16 row-major, B [N,K0] fp16 K-major. Single pass.
// Tile 128x128, BK=64, 8 warps (64x32), 2-stage cp.async double buffer.
// EPI 0 (gemm1): +bias+hs, fp16 out. EPI 1 (gemm2): +bias, exp(), fp32 out,
//   per-(b,col) exp-sums accumulated into g_sum via smem bins + atomicAdd.

__device__ __forceinline__ void load_tile_async(uint32_t dst, const f16* src,
                                                int ldk, int tid) {
#pragma unroll
    for (int i = 0; i < 4; ++i) {
        int chunk = i * 256 + tid;
        int r = chunk >> 3, c16 = chunk & 7;
        const char* g = (const char*)src + (size_t)r * ldk * 2 + c16 * 16;
        uint32_t s = dst + r * 128 + ((c16 * 16) ^ ((r & 7) << 4));
        cp_async16(s, g);
    }
}

template <int EPI>
__global__ __launch_bounds__(256, 2)
void mma_gemm(const f16* __restrict__ Ah, const f16* __restrict__ Bh,
              const float* __restrict__ bias,
              float* __restrict__ Cf, f16* __restrict__ Ch,
              int N, int K0) {
    extern __shared__ char smem[];
    uint32_t sbase = smem_u32(smem);
    int tid = threadIdx.x, lane = tid & 31, wid = tid >> 5;
    int warp_m = wid >> 2, warp_n = wid & 3;
    int row0 = blockIdx.y * 128, col0 = blockIdx.x * 128;

    float c[4][4][4];
#pragma unroll
    for (int mi = 0; mi < 4; ++mi)
#pragma unroll
        for (int ni = 0; ni < 4; ++ni)
#pragma unroll
            for (int f = 0; f < 4; ++f) c[mi][ni][f] = 0.f;

    int nch = K0 / 64;

    auto issue = [&](int cc) {
        int buf = cc & 1;
        int kk = cc * 64;
        load_tile_async(sbase + buf * 32768, Ah + (size_t)row0 * K0 + kk, K0, tid);
        load_tile_async(sbase + buf * 32768 + 16384, Bh + (size_t)col0 * K0 + kk, K0, tid);
        cp_commit();
    };

    issue(0);

    int la15 = lane & 15, la7 = lane & 7;
    int a_cbsel = (lane >> 4) * 16;
    int b_cbsel = ((lane >> 3) & 1) * 16;
    int b_rowsel = (lane >> 4) * 8;

    for (int cc = 0; cc < nch; ++cc) {
        if (cc + 1 < nch) { issue(cc + 1); cp_wait1(); }
        else              { cp_wait0(); }
        __syncthreads();

        uint32_t sA = sbase + (cc & 1) * 32768;
        uint32_t sB = sA + 16384;
#pragma unroll
        for (int ks = 0; ks < 4; ++ks) {
            uint32_t a[4][4];
#pragma unroll
            for (int mi = 0; mi < 4; ++mi) {
                int row = warp_m * 64 + mi * 16 + la15;
                uint32_t cb = ks * 32 + a_cbsel;
                ldsm4(a[mi][0], a[mi][1], a[mi][2], a[mi][3],
                      sA + row * 128 + (cb ^ ((row & 7) << 4)));
            }
            uint32_t b[4][2];
#pragma unroll
            for (int nb = 0; nb < 2; ++nb) {
                int row = warp_n * 32 + nb * 16 + la7 + b_rowsel;
                uint32_t cb = ks * 32 + b_cbsel;
                ldsm4(b[2 * nb][0], b[2 * nb][1], b[2 * nb + 1][0], b[2 * nb + 1][1],
                      sB + row * 128 + (cb ^ ((row & 7) << 4)));
            }
#pragma unroll
            for (int mi = 0; mi < 4; ++mi)
#pragma unroll
                for (int ni = 0; ni < 4; ++ni)
                    mma16816(c[mi][ni], a[mi], b[ni]);
        }
        __syncthreads();
    }

    // ---------------- epilogue ----------------
    float* bins = (float*)smem;   // 256 floats: [seg][col_local]
    int b0 = 0, bsplit = 0;
    if (EPI == 1) {
        if (tid < 256) bins[tid] = 0.f;
        b0 = row0 / LL;
        bsplit = (b0 + 1) * LL;
        __syncthreads();
    }

    int g = lane >> 2, tg = lane & 3;
#pragma unroll
    for (int mi = 0; mi < 4; ++mi) {
#pragma unroll
        for (int half = 0; half < 2; ++half) {
            int row = row0 + warp_m * 64 + mi * 16 + g + half * 8;
            const float* hsrow = (EPI == 0) ? (g_hs + (size_t)(row / LL) * II) : nullptr;
            int seg = (EPI == 1 && row >= bsplit) ? 1 : 0;
#pragma unroll
            for (int ni = 0; ni < 4; ++ni) {
                int cl = warp_n * 32 + ni * 8 + tg * 2;
                int col = col0 + cl;
                float v0 = c[mi][ni][2 * half + 0] + bias[col];
                float v1 = c[mi][ni][2 * half + 1] + bias[col + 1];
                if (EPI == 0) {
                    v0 += hsrow[col];
                    v1 += hsrow[col + 1];
                    *(__half2*)(Ch + (size_t)row * N + col) = __floats2half2_rn(v0, v1);
                } else {
                    float e0 = __expf(v0), e1 = __expf(v1);
                    *(float2*)(Cf + (size_t)row * N + col) = make_float2(e0, e1);
                    atomicAdd(&bins[seg * 128 + cl], e0);
                    atomicAdd(&bins[seg * 128 + cl + 1], e1);
                }
            }
        }
    }

    if (EPI == 1) {
        __syncthreads();
        if (tid < 256) {
            float v = bins[tid];
            if (v != 0.f) {
                int seg = tid >> 7, cl = tid & 127;
                atomicAdd(&g_sum[(size_t)(b0 + seg) * DD + col0 + cl], v);
            }
        }
    }
}

// ---------------- normalize + z (single pass) ----------------
// e region already holds exp(e); g_sum holds denominators.
__global__ __launch_bounds__(128)
void norm_z_kernel(float* __restrict__ out) {
    int idx = blockIdx.x * blockDim.x + threadIdx.x;   // 0..BB*DD/2
    int b = idx / (DD / 2);
    int dp = idx % (DD / 2);
    float2* e        = (float2*)(out + BB * DD + (size_t)b * LL * DD) + dp;
    const __half2* f = ((const __half2*)g_fv_h) + (size_t)b * LL * (DD / 2) + dp;
    const int str = DD / 2;

    float2 sv = ((const float2*)(g_sum + (size_t)b * DD))[dp];
    float2 inv = make_float2(1.f / sv.x, 1.f / sv.y);
    float2 z = make_float2(0.f, 0.f);
    for (int l = 0; l < LL; ++l) {
        size_t off = (size_t)l * str;
        float2 v = e[off];
        float2 fw = __half22float2(f[off]);
        float2 p = make_float2(v.x * inv.x, v.y * inv.y);
        e[off] = p;
        z.x = fmaf(p.x, fw.x, z.x);
        z.y = fmaf(p.y, fw.y, z.y);
    }
    ((float2*)out)[idx] = z;
}

// ---------------- launch ----------------
#define GEMM_SMEM 65536

extern "C" void kernel_launch(void* const* d_in, const int* in_sizes, int n_in,
                              void* d_out, int out_size) {
    const float* fv     = (const float*)d_in[0];
    const float* hidden = (const float*)d_in[1];
    const float* Wf     = (const float*)d_in[2];
    const float* bf     = (const float*)d_in[3];
    const float* Wh     = (const float*)d_in[4];
    const float* bh     = (const float*)d_in[5];
    const float* Wa     = (const float*)d_in[6];
    const float* ba     = (const float*)d_in[7];
    float* out = (float*)d_out;

    cudaFuncSetAttribute(mma_gemm<0>, cudaFuncAttributeMaxDynamicSharedMemorySize, GEMM_SMEM);
    cudaFuncSetAttribute(mma_gemm<1>, cudaFuncAttributeMaxDynamicSharedMemorySize, GEMM_SMEM);

    void* p;
    cudaGetSymbolAddress(&p, g_fv_h);    f16* fv_h   = (f16*)p;
    cudaGetSymbolAddress(&p, g_fvs_h);   f16* fvs_h  = (f16*)p;
    cudaGetSymbolAddress(&p, g_WfT_h);   f16* WfT_h  = (f16*)p;
    cudaGetSymbolAddress(&p, g_WaT_h);   f16* WaT_h  = (f16*)p;
    void* sum_ptr; cudaGetSymbolAddress(&sum_ptr, g_sum);

    // all input conversions in one launch; zero softmax denominators
    prep_kernel<<<PREP_BLOCKS, 256>>>(fv, hidden, Wh, bh, Wf, Wa);
    cudaMemsetAsync(sum_ptr, 0, BB * DD * sizeof(float));

    // gemm1: fvs = fv @ Wf + bf + hs   (M=12544, N=512, K0=2048) -> fp16
    mma_gemm<0><<<dim3(II / 128, MM / 128), 256, GEMM_SMEM>>>(
        fv_h, WfT_h, bf, nullptr, fvs_h, II, DD);

    // gemm2: exp(e) = exp(fvs @ Wa + ba) -> fp32 into alpha region + g_sum
    float* e = out + BB * DD;
    mma_gemm<1><<<dim3(DD / 128, MM / 128), 256, GEMM_SMEM>>>(
        fvs_h, WaT_h, ba, e, nullptr, DD, II);

    // normalize (in place) + z
    norm_z_kernel<<<BB * DD / 2 / 128, 128>>>(out);
}

// round 13
// speedup vs baseline: 1.5574x; 1.5574x over previous
#include <cuda_runtime.h>
#include <cuda_fp16.h>
#include <stdint.h>
#include <math.h>

#define BB 64
#define LL 196
#define DD 2048
#define II 512
#define MM (BB * LL)   // 12544

typedef __half f16;

// ---------------- device scratch (allocation-free) ----------------
__device__ f16 g_fv_h[(size_t)MM * DD];
__device__ f16 g_fvs_h[(size_t)MM * II];
__device__ f16 g_WfT_h[(size_t)II * DD];   // [I, D] K-major
__device__ f16 g_WaT_h[(size_t)DD * II];   // [D, I] K-major
__device__ float g_hs[BB * II];

// ---------------- helpers ----------------
__device__ __forceinline__ uint32_t smem_u32(const void* p) {
    uint32_t a;
    asm("{ .reg .u64 t; cvta.to.shared.u64 t, %1; cvt.u32.u64 %0, t; }"
        : "=r"(a) : "l"(p));
    return a;
}
__device__ __forceinline__ void cp_async16(uint32_t s, const void* g) {
    asm volatile("cp.async.cg.shared.global [%0], [%1], 16;" :: "r"(s), "l"(g));
}
__device__ __forceinline__ void cp_commit() {
    asm volatile("cp.async.commit_group;" ::: "memory");
}
__device__ __forceinline__ void cp_wait1() {
    asm volatile("cp.async.wait_group 1;" ::: "memory");
}
__device__ __forceinline__ void cp_wait0() {
    asm volatile("cp.async.wait_group 0;" ::: "memory");
}
__device__ __forceinline__ void ldsm4(uint32_t& r0, uint32_t& r1, uint32_t& r2,
                                      uint32_t& r3, uint32_t addr) {
    asm volatile("ldmatrix.sync.aligned.m8n8.x4.shared.b16 {%0,%1,%2,%3}, [%4];"
                 : "=r"(r0), "=r"(r1), "=r"(r2), "=r"(r3) : "r"(addr));
}
__device__ __forceinline__ void mma16816(float* c, const uint32_t* a,
                                         const uint32_t* b) {
    asm volatile(
        "mma.sync.aligned.m16n8k16.row.col.f32.f16.f16.f32 "
        "{%0,%1,%2,%3}, {%4,%5,%6,%7}, {%8,%9}, {%0,%1,%2,%3};"
        : "+f"(c[0]), "+f"(c[1]), "+f"(c[2]), "+f"(c[3])
        : "r"(a[0]), "r"(a[1]), "r"(a[2]), "r"(a[3]), "r"(b[0]), "r"(b[1]));
}

// ---------------- fused prep kernel ----------------
// blocks [0,1024): transpose Wf [2048,512] -> WfT [512,2048]
// blocks [1024,2048): transpose Wa [512,2048] -> WaT [2048,512]
// blocks [2048,2176): hs = hidden @ Wh + bh
// blocks [2176,...): fv -> fp16
__device__ __forceinline__ void transpose_body(const float* __restrict__ in,
                                               f16* __restrict__ oh,
                                               int K, int N, int bx, int by,
                                               int tid, float (*t)[33]) {
    int n0 = bx * 32, k0 = by * 32;
    int tx = tid & 31, ty = tid >> 5;   // (32, 8)
#pragma unroll
    for (int i = 0; i < 32; i += 8)
        t[ty + i][tx] = in[(size_t)(k0 + ty + i) * N + n0 + tx];
    __syncthreads();
#pragma unroll
    for (int i = 0; i < 32; i += 8)
        oh[(size_t)(n0 + ty + i) * K + k0 + tx] = __float2half_rn(t[tx][ty + i]);
}

__global__ __launch_bounds__(256)
void prep_kernel(const float* __restrict__ fv, const float* __restrict__ hidden,
                 const float* __restrict__ Wh, const float* __restrict__ bh,
                 const float* __restrict__ Wf, const float* __restrict__ Wa) {
    __shared__ float t[32][33];
    int blk = blockIdx.x, tid = threadIdx.x;
    if (blk < 1024) {
        transpose_body(Wf, g_WfT_h, DD, II, blk & 15, blk >> 4, tid, t);
    } else if (blk < 2048) {
        int bb = blk - 1024;
        transpose_body(Wa, g_WaT_h, II, DD, bb & 63, bb >> 6, tid, t);
    } else if (blk < 2176) {
        int idx = (blk - 2048) * 256 + tid;   // 0..BB*II
        int b = idx >> 9, i = idx & 511;
        const float* h = hidden + b * II;
        float acc = bh[i];
#pragma unroll 4
        for (int j = 0; j < II; ++j)
            acc = fmaf(h[j], Wh[j * II + i], acc);
        g_hs[idx] = acc;
    } else {
        size_t i = (size_t)(blk - 2176) * 256 + tid;   // over MM*DD/4
        float4 v = ((const float4*)fv)[i];
        ((__half2*)g_fv_h)[2 * i]     = __floats2half2_rn(v.x, v.y);
        ((__half2*)g_fv_h)[2 * i + 1] = __floats2half2_rn(v.z, v.w);
    }
}
#define PREP_BLOCKS (2176 + (MM * DD / 4) / 256)

// ---------------- tensor-core (mma.sync) GEMM ----------------
// C = A@B^T; A [M,K0] fp16 row-major, B [N,K0] fp16 K-major. Single pass.
// Tile 128x128, BK=64, 8 warps (64x32), 2-stage cp.async double buffer.
// Smem row: 128B (64 f16), swizzle byteoff = row*128 + (cb ^ ((row&7)<<4)).

__device__ __forceinline__ void load_tile_async(uint32_t dst, const f16* src,
                                                int ldk, int tid) {
#pragma unroll
    for (int i = 0; i < 4; ++i) {
        int chunk = i * 256 + tid;
        int r = chunk >> 3, c16 = chunk & 7;
        const char* g = (const char*)src + (size_t)r * ldk * 2 + c16 * 16;
        uint32_t s = dst + r * 128 + ((c16 * 16) ^ ((r & 7) << 4));
        cp_async16(s, g);
    }
}

template <int EPI>
__global__ __launch_bounds__(256, 2)
void mma_gemm(const f16* __restrict__ Ah, const f16* __restrict__ Bh,
              const float* __restrict__ bias,
              float* __restrict__ Cf, f16* __restrict__ Ch,
              int N, int K0) {
    extern __shared__ char smem[];
    uint32_t sbase = smem_u32(smem);
    int tid = threadIdx.x, lane = tid & 31, wid = tid >> 5;
    int warp_m = wid >> 2, warp_n = wid & 3;
    int row0 = blockIdx.y * 128, col0 = blockIdx.x * 128;

    float c[4][4][4];
#pragma unroll
    for (int mi = 0; mi < 4; ++mi)
#pragma unroll
        for (int ni = 0; ni < 4; ++ni)
#pragma unroll
            for (int f = 0; f < 4; ++f) c[mi][ni][f] = 0.f;

    int nch = K0 / 64;

    auto issue = [&](int cc) {
        int buf = cc & 1;
        int kk = cc * 64;
        load_tile_async(sbase + buf * 32768, Ah + (size_t)row0 * K0 + kk, K0, tid);
        load_tile_async(sbase + buf * 32768 + 16384, Bh + (size_t)col0 * K0 + kk, K0, tid);
        cp_commit();
    };

    issue(0);

    int la15 = lane & 15, la7 = lane & 7;
    int a_cbsel = (lane >> 4) * 16;
    int b_cbsel = ((lane >> 3) & 1) * 16;
    int b_rowsel = (lane >> 4) * 8;

    for (int cc = 0; cc < nch; ++cc) {
        if (cc + 1 < nch) { issue(cc + 1); cp_wait1(); }
        else              { cp_wait0(); }
        __syncthreads();

        uint32_t sA = sbase + (cc & 1) * 32768;
        uint32_t sB = sA + 16384;
#pragma unroll
        for (int ks = 0; ks < 4; ++ks) {
            uint32_t a[4][4];
#pragma unroll
            for (int mi = 0; mi < 4; ++mi) {
                int row = warp_m * 64 + mi * 16 + la15;
                uint32_t cb = ks * 32 + a_cbsel;
                ldsm4(a[mi][0], a[mi][1], a[mi][2], a[mi][3],
                      sA + row * 128 + (cb ^ ((row & 7) << 4)));
            }
            uint32_t b[4][2];
#pragma unroll
            for (int nb = 0; nb < 2; ++nb) {
                int row = warp_n * 32 + nb * 16 + la7 + b_rowsel;
                uint32_t cb = ks * 32 + b_cbsel;
                ldsm4(b[2 * nb][0], b[2 * nb][1], b[2 * nb + 1][0], b[2 * nb + 1][1],
                      sB + row * 128 + (cb ^ ((row & 7) << 4)));
            }
#pragma unroll
            for (int mi = 0; mi < 4; ++mi)
#pragma unroll
                for (int ni = 0; ni < 4; ++ni)
                    mma16816(c[mi][ni], a[mi], b[ni]);
        }
        __syncthreads();
    }

    // ---------------- epilogue ----------------
    int g = lane >> 2, tg = lane & 3;
#pragma unroll
    for (int mi = 0; mi < 4; ++mi) {
#pragma unroll
        for (int half = 0; half < 2; ++half) {
            int row = row0 + warp_m * 64 + mi * 16 + g + half * 8;
            const float* hsrow = (EPI == 0) ? (g_hs + (size_t)(row / LL) * II) : nullptr;
#pragma unroll
            for (int ni = 0; ni < 4; ++ni) {
                int col = col0 + warp_n * 32 + ni * 8 + tg * 2;
                float v0 = c[mi][ni][2 * half + 0];
                float v1 = c[mi][ni][2 * half + 1];
                v0 += bias[col];
                v1 += bias[col + 1];
                if (EPI == 0) {
                    v0 += hsrow[col];
                    v1 += hsrow[col + 1];
                    *(__half2*)(Ch + (size_t)row * N + col) = __floats2half2_rn(v0, v1);
                } else {
                    *(float2*)(Cf + (size_t)row * N + col) = make_float2(v0, v1);
                }
            }
        }
    }
}

// ---------------- softmax + z (L split 2-way per (b,d) pair) ----------------
// CTA = 128 threads handles 64 float2-lanes; threads t and t^64 share a lane,
// each covering 98 of the 196 L rows. exp without max (|e| small). Two passes:
// (1) sum of exp, smem-combine; (2) normalize + z partial, smem-combine.
__global__ __launch_bounds__(128)
void softmax_z_kernel(float* __restrict__ out) {
    __shared__ float2 sh[128];
    int t = threadIdx.x;
    int pairi = blockIdx.x * 64 + (t & 63);
    int half = t >> 6;
    int b = pairi / (DD / 2);
    int dp = pairi % (DD / 2);
    float2* e        = (float2*)(out + BB * DD + (size_t)b * LL * DD) + dp;
    const __half2* f = ((const __half2*)g_fv_h) + (size_t)b * LL * (DD / 2) + dp;
    const int str = DD / 2;
    int l0 = half * 98;

    float2 s = make_float2(0.f, 0.f);
    for (int l = l0; l < l0 + 98; ++l) {
        float2 v = e[(size_t)l * str];
        s.x += __expf(v.x);
        s.y += __expf(v.y);
    }
    sh[t] = s;
    __syncthreads();
    float2 o = sh[t ^ 64];
    float2 inv = make_float2(1.f / (s.x + o.x), 1.f / (s.y + o.y));

    float2 z = make_float2(0.f, 0.f);
    for (int l = l0; l < l0 + 98; ++l) {
        size_t off = (size_t)l * str;
        float2 v = e[off];
        float2 fw = __half22float2(f[off]);
        float2 p = make_float2(__expf(v.x) * inv.x, __expf(v.y) * inv.y);
        e[off] = p;
        z.x = fmaf(p.x, fw.x, z.x);
        z.y = fmaf(p.y, fw.y, z.y);
    }
    __syncthreads();
    sh[t] = z;
    __syncthreads();
    if (half == 0) {
        float2 zo = sh[t + 64];
        ((float2*)out)[pairi] = make_float2(z.x + zo.x, z.y + zo.y);
    }
}

// ---------------- launch ----------------
#define GEMM_SMEM 65536

extern "C" void kernel_launch(void* const* d_in, const int* in_sizes, int n_in,
                              void* d_out, int out_size) {
    const float* fv     = (const float*)d_in[0];
    const float* hidden = (const float*)d_in[1];
    const float* Wf     = (const float*)d_in[2];
    const float* bf     = (const float*)d_in[3];
    const float* Wh     = (const float*)d_in[4];
    const float* bh     = (const float*)d_in[5];
    const float* Wa     = (const float*)d_in[6];
    const float* ba     = (const float*)d_in[7];
    float* out = (float*)d_out;

    cudaFuncSetAttribute(mma_gemm<0>, cudaFuncAttributeMaxDynamicSharedMemorySize, GEMM_SMEM);
    cudaFuncSetAttribute(mma_gemm<1>, cudaFuncAttributeMaxDynamicSharedMemorySize, GEMM_SMEM);

    void* p;
    cudaGetSymbolAddress(&p, g_fv_h);    f16* fv_h  = (f16*)p;
    cudaGetSymbolAddress(&p, g_fvs_h);   f16* fvs_h = (f16*)p;
    cudaGetSymbolAddress(&p, g_WfT_h);   f16* WfT_h = (f16*)p;
    cudaGetSymbolAddress(&p, g_WaT_h);   f16* WaT_h = (f16*)p;

    // all input conversions in one launch
    prep_kernel<<<PREP_BLOCKS, 256>>>(fv, hidden, Wh, bh, Wf, Wa);

    // gemm1: fvs = fv @ Wf + bf + hs   (M=12544, N=512, K0=2048) -> fp16
    mma_gemm<0><<<dim3(II / 128, MM / 128), 256, GEMM_SMEM>>>(
        fv_h, WfT_h, bf, nullptr, fvs_h, II, DD);

    // gemm2: e = fvs @ Wa + ba   (M=12544, N=2048, K0=512) -> fp32 into out
    float* e = out + BB * DD;
    mma_gemm<1><<<dim3(DD / 128, MM / 128), 256, GEMM_SMEM>>>(
        fvs_h, WaT_h, ba, e, nullptr, DD, II);

    // softmax over L (in place) + z
    softmax_z_kernel<<<BB * DD / 2 / 64, 128>>>(out);
}